// round 15
// baseline (speedup 1.0000x reference)
#include <cuda_runtime.h>
#include <math.h>

#define BLK 64
#define NJ 12

typedef unsigned long long u64;

__device__ __forceinline__ u64 fma2(u64 a, u64 b, u64 c) {
    u64 d; asm("fma.rn.f32x2 %0, %1, %2, %3;" : "=l"(d) : "l"(a), "l"(b), "l"(c)); return d;
}
__device__ __forceinline__ u64 mul2(u64 a, u64 b) {
    u64 d; asm("mul.rn.f32x2 %0, %1, %2;" : "=l"(d) : "l"(a), "l"(b)); return d;
}
__device__ __forceinline__ u64 add2(u64 a, u64 b) {
    u64 d; asm("add.rn.f32x2 %0, %1, %2;" : "=l"(d) : "l"(a), "l"(b)); return d;
}
__device__ __forceinline__ u64 pack2(float lo, float hi) {
    u64 d; asm("mov.b64 %0, {%1, %2};" : "=l"(d) : "f"(lo), "f"(hi)); return d;
}
__device__ __forceinline__ void unpack2(u64 a, float& lo, float& hi) {
    asm("mov.b64 {%0, %1}, %2;" : "=f"(lo), "=f"(hi) : "l"(a));
}
__device__ __forceinline__ float hr0(u64 acc) {   // bias pre-folded into acc
    float lo, hi; unpack2(acc, lo, hi);
    return fmaxf(lo + hi, 0.0f);
}
__device__ __forceinline__ u64 relu2(u64 a) {
    float lo, hi; unpack2(a, lo, hi);
    return pack2(fmaxf(lo, 0.0f), fmaxf(hi, 0.0f));
}

#define ONE2  0x3F8000003F800000ULL
#define ZERO2 0ULL

// Dot-packed layer for TWO elements; SINGLE accumulator chain per dot
// product (4 chains per output pair), bias folded into chain init.
template<int OUT, int IN>
__device__ __forceinline__ void dotlayer(const float* __restrict__ sW,
                                         const float* __restrict__ sB,
                                         const u64* __restrict__ hA,
                                         const u64* __restrict__ hB,
                                         u64* __restrict__ outA,
                                         u64* __restrict__ outB) {
    #pragma unroll
    for (int o = 0; o < OUT; o += 2) {
        const u64 bi0 = pack2(sB[o], 0.0f);
        const u64 bi1 = pack2(sB[o + 1], 0.0f);
        u64 aA = bi0, bA = bi1, aB = bi0, bB = bi1;
        const float* r0 = sW + o * IN;
        const float* r1 = r0 + IN;
        #pragma unroll
        for (int k = 0; k < IN; k += 4) {
            const ulonglong2 w0 = *reinterpret_cast<const ulonglong2*>(r0 + k);
            const ulonglong2 w1 = *reinterpret_cast<const ulonglong2*>(r1 + k);
            const u64 hAa = hA[k / 2], hAb = hA[k / 2 + 1];
            const u64 hBa = hB[k / 2], hBb = hB[k / 2 + 1];
            aA = fma2(w0.x, hAa, aA);  aA = fma2(w0.y, hAb, aA);
            aB = fma2(w0.x, hBa, aB);  aB = fma2(w0.y, hBb, aB);
            bA = fma2(w1.x, hAa, bA);  bA = fma2(w1.y, hAb, bA);
            bB = fma2(w1.x, hBa, bB);  bB = fma2(w1.y, hBb, bB);
        }
        outA[o / 2] = pack2(hr0(aA), hr0(bA));
        outB[o / 2] = pack2(hr0(aB), hr0(bB));
    }
}

__global__ __launch_bounds__(BLK, 7)
void fk_kernel(const float* __restrict__ mc,
               const float* __restrict__ W1, const float* __restrict__ b1,
               const float* __restrict__ W2, const float* __restrict__ b2,
               const float* __restrict__ W3, const float* __restrict__ b3,
               const float* __restrict__ W4, const float* __restrict__ b4,
               const float* __restrict__ W5, const float* __restrict__ b5,
               const float* __restrict__ twist,
               const float* __restrict__ init_p,
               const float* __restrict__ init_rpy,
               float* __restrict__ out, int B)
{
    __shared__ __align__(16) float sW1[16 * 4];
    __shared__ __align__(16) float sW2[32 * 16];
    __shared__ __align__(16) float sW3[64 * 32];
    __shared__ __align__(16) float sW4T[64 * 32];  // plain transposed [k][o]
    __shared__ __align__(16) float sW5[12 * 32];
    __shared__ float sB1[16], sB2[32], sB3[64];
    __shared__ __align__(8) float sB4[32];
    __shared__ float sB5[12];
    __shared__ u64 sjwn[NJ];
    __shared__ u64 sjru[NJ][3], sjKru[NJ][3], sjK2ru[NJ][3];
    __shared__ u64 sjK[NJ][9], sjK2[NJ][9];
    __shared__ u64 sT0[12];

    const int tid = threadIdx.x;

    for (int t = tid; t < 16 * 4;  t += BLK) sW1[t] = W1[t];
    for (int t = tid; t < 32 * 16; t += BLK) sW2[t] = W2[t];
    for (int t = tid; t < 64 * 32; t += BLK) sW3[t] = W3[t];
    for (int t = tid; t < 12 * 32; t += BLK) sW5[t] = W5[t];
    for (int t = tid; t < 32 * 64; t += BLK) {
        const int o = t & 31;
        const int k = t >> 5;
        sW4T[t] = W4[o * 64 + k];
    }
    for (int t = tid; t < 16; t += BLK) sB1[t] = b1[t];
    for (int t = tid; t < 32; t += BLK) sB2[t] = b2[t];
    for (int t = tid; t < 64; t += BLK) sB3[t] = b3[t];
    for (int t = tid; t < 32; t += BLK) sB4[t] = b4[t];
    for (int t = tid; t < 12; t += BLK) sB5[t] = b5[t];

    if (tid < NJ) {
        const float* tw = twist + tid * 6;
        float rx = tw[0], ry = tw[1], rz = tw[2];
        float wx = tw[3], wy = tw[4], wz = tw[5];
        float wn  = sqrtf(wx * wx + wy * wy + wz * wz + 1e-12f);
        float inv = 1.0f / wn;
        float ux = wx * inv, uy = wy * inv, uz = wz * inv;
        float rux = rx * inv, ruy = ry * inv, ruz = rz * inv;
        float K[9] = { 0.f, -uz,  uy,
                       uz,  0.f, -ux,
                      -uy,  ux,  0.f };
        float K2[9];
        #pragma unroll
        for (int a = 0; a < 3; a++)
            #pragma unroll
            for (int bb = 0; bb < 3; bb++)
                K2[a*3+bb] = K[a*3+0]*K[0*3+bb] + K[a*3+1]*K[1*3+bb] + K[a*3+2]*K[2*3+bb];
        sjwn[tid] = pack2(wn, wn);
        sjru[tid][0] = pack2(rux, rux); sjru[tid][1] = pack2(ruy, ruy); sjru[tid][2] = pack2(ruz, ruz);
        #pragma unroll
        for (int a = 0; a < 3; a++) {
            float kr  = K[a*3+0]*rux  + K[a*3+1]*ruy  + K[a*3+2]*ruz;
            float k2r = K2[a*3+0]*rux + K2[a*3+1]*ruy + K2[a*3+2]*ruz;
            sjKru[tid][a]  = pack2(kr, kr);
            sjK2ru[tid][a] = pack2(k2r, k2r);
        }
        #pragma unroll
        for (int e = 0; e < 9; e++) {
            sjK[tid][e]  = pack2(K[e], K[e]);
            sjK2[tid][e] = pack2(K2[e], K2[e]);
        }
    }
    if (tid == 32) {
        float r = init_rpy[0], p = init_rpy[1], y = init_rpy[2];
        float cr = cosf(r), sr = sinf(r);
        float cp = cosf(p), sp = sinf(p);
        float cy = cosf(y), sy = sinf(y);
        float T0[12] = {
            cy*cp,  cy*sp*sr - sy*cr,  cy*sp*cr + sy*sr,  init_p[0],
            sy*cp,  sy*sp*sr + cy*cr,  sy*sp*cr - cy*sr,  init_p[1],
            -sp,    cp*sr,             cp*cr,             init_p[2] };
        #pragma unroll
        for (int e = 0; e < 12; e++) sT0[e] = pack2(T0[e], T0[e]);
    }
    __syncthreads();

    const int i0 = blockIdx.x * (2 * BLK) + tid;
    if (i0 >= B) return;
    int i1 = i0 + BLK;
    if (i1 >= B) i1 = B - 1;   // duplicate-safe

    const float4 a0 = reinterpret_cast<const float4*>(mc)[i0];
    const float4 a1 = reinterpret_cast<const float4*>(mc)[i1];
    u64 xA[2] = { pack2(a0.x, a0.y), pack2(a0.z, a0.w) };
    u64 xB[2] = { pack2(a1.x, a1.y), pack2(a1.z, a1.w) };

    u64 h1A[8],  h1B[8];  dotlayer<16, 4 >(sW1, sB1, xA,  xB,  h1A, h1B);
    u64 h2A[16], h2B[16]; dotlayer<32, 16>(sW2, sB2, h1A, h1B, h2A, h2B);

    // ---- fused L3 -> L4: ONE h3 feature per iteration, minimal live temps ----
    u64 accA[16], accB[16];
    {
        const u64* sb4p = reinterpret_cast<const u64*>(sB4);
        #pragma unroll
        for (int o = 0; o < 16; o++) { accA[o] = sb4p[o]; accB[o] = sb4p[o]; }
    }

    #pragma unroll
    for (int c = 0; c < 64; c++) {
        const u64 bi = pack2(sB3[c], 0.0f);
        u64 aA = bi, aB = bi;                 // 2 chains (A, B)
        const float* r0 = sW3 + c * 32;
        #pragma unroll
        for (int k = 0; k < 32; k += 4) {
            const ulonglong2 w = *reinterpret_cast<const ulonglong2*>(r0 + k);
            aA = fma2(w.x, h2A[k / 2],     aA);
            aA = fma2(w.y, h2A[k / 2 + 1], aA);
            aB = fma2(w.x, h2B[k / 2],     aB);
            aB = fma2(w.y, h2B[k / 2 + 1], aB);
        }
        const float vA = hr0(aA);
        const float vB = hr0(aB);
        const u64 dA = pack2(vA, vA);
        const u64 dB = pack2(vB, vB);

        const float* wr = sW4T + c * 32;
        #pragma unroll
        for (int o = 0; o < 32; o += 4) {
            const ulonglong2 w = *reinterpret_cast<const ulonglong2*>(wr + o);
            accA[o / 2]     = fma2(w.x, dA, accA[o / 2]);
            accA[o / 2 + 1] = fma2(w.y, dA, accA[o / 2 + 1]);
            accB[o / 2]     = fma2(w.x, dB, accB[o / 2]);
            accB[o / 2 + 1] = fma2(w.y, dB, accB[o / 2 + 1]);
        }
    }

    // relu in place — acc already has bias, already feature-pair layout
    u64 h4A[16], h4B[16];
    #pragma unroll
    for (int i = 0; i < 16; i++) {
        h4A[i] = relu2(accA[i]);
        h4B[i] = relu2(accB[i]);
    }

    // L5 -> element-packed q (single-chain accumulators)
    u64 qv[NJ];
    #pragma unroll
    for (int o = 0; o < 12; o += 2) {
        const u64 bi0 = pack2(sB5[o], 0.0f);
        const u64 bi1 = pack2(sB5[o + 1], 0.0f);
        u64 aA = bi0, bA = bi1, aB = bi0, bB = bi1;
        const float* r0 = sW5 + o * 32;
        const float* r1 = r0 + 32;
        #pragma unroll
        for (int k = 0; k < 32; k += 4) {
            const ulonglong2 w0 = *reinterpret_cast<const ulonglong2*>(r0 + k);
            const ulonglong2 w1 = *reinterpret_cast<const ulonglong2*>(r1 + k);
            const u64 hAa = h4A[k / 2], hAb = h4A[k / 2 + 1];
            const u64 hBa = h4B[k / 2], hBb = h4B[k / 2 + 1];
            aA = fma2(w0.x, hAa, aA);  aA = fma2(w0.y, hAb, aA);
            aB = fma2(w0.x, hBa, aB);  aB = fma2(w0.y, hBb, aB);
            bA = fma2(w1.x, hAa, bA);  bA = fma2(w1.y, hAb, bA);
            bB = fma2(w1.x, hBa, bB);  bB = fma2(w1.y, hBb, bB);
        }
        qv[o]     = pack2(hr0(aA), hr0(aB));
        qv[o + 1] = pack2(hr0(bA), hr0(bB));
    }

    // ---- element-packed SE(3) chain ----
    u64 T[12] = { ONE2, ZERO2, ZERO2, ZERO2,
                  ZERO2, ONE2, ZERO2, ZERO2,
                  ZERO2, ZERO2, ONE2, ZERO2 };
    #pragma unroll
    for (int j = 0; j < NJ; j++) {
        const u64 th2 = mul2(qv[j], sjwn[j]);
        float th0, th1; unpack2(th2, th0, th1);
        float s0, co0, s1, co1;
        __sincosf(th0, &s0, &co0);
        __sincosf(th1, &s1, &co1);
        const u64 s2 = pack2(s0, s1);
        const u64 c2 = pack2(1.0f - co0, 1.0f - co1);
        const u64 t2 = pack2(th0 - s0, th1 - s1);

        u64 R[9];
        #pragma unroll
        for (int e = 0; e < 9; e++) {
            const u64 d = (e == 0 || e == 4 || e == 8) ? ONE2 : ZERO2;
            R[e] = fma2(s2, sjK[j][e], fma2(c2, sjK2[j][e], d));
        }
        const u64 p0 = fma2(th2, sjru[j][0], fma2(c2, sjKru[j][0], mul2(t2, sjK2ru[j][0])));
        const u64 p1 = fma2(th2, sjru[j][1], fma2(c2, sjKru[j][1], mul2(t2, sjK2ru[j][1])));
        const u64 p2 = fma2(th2, sjru[j][2], fma2(c2, sjKru[j][2], mul2(t2, sjK2ru[j][2])));

        u64 N[12];
        #pragma unroll
        for (int r = 0; r < 3; r++) {
            const u64 a0r = T[r*4+0], a1r = T[r*4+1], a2r = T[r*4+2], a3r = T[r*4+3];
            N[r*4+0] = fma2(a0r, R[0], fma2(a1r, R[3], mul2(a2r, R[6])));
            N[r*4+1] = fma2(a0r, R[1], fma2(a1r, R[4], mul2(a2r, R[7])));
            N[r*4+2] = fma2(a0r, R[2], fma2(a1r, R[5], mul2(a2r, R[8])));
            N[r*4+3] = fma2(a0r, p0,  fma2(a1r, p1,  fma2(a2r, p2, a3r)));
        }
        #pragma unroll
        for (int e = 0; e < 12; e++) T[e] = N[e];
    }

    float4* op0 = reinterpret_cast<float4*>(out + (size_t)i0 * 16);
    float4* op1 = reinterpret_cast<float4*>(out + (size_t)i1 * 16);
    #pragma unroll
    for (int r = 0; r < 3; r++) {
        const u64 a0r = T[r*4+0], a1r = T[r*4+1], a2r = T[r*4+2], a3r = T[r*4+3];
        const u64 vx = fma2(a0r, sT0[0], fma2(a1r, sT0[4], mul2(a2r, sT0[8])));
        const u64 vy = fma2(a0r, sT0[1], fma2(a1r, sT0[5], mul2(a2r, sT0[9])));
        const u64 vz = fma2(a0r, sT0[2], fma2(a1r, sT0[6], mul2(a2r, sT0[10])));
        const u64 vw = fma2(a0r, sT0[3], fma2(a1r, sT0[7], fma2(a2r, sT0[11], a3r)));
        float4 r0, r1;
        unpack2(vx, r0.x, r1.x);
        unpack2(vy, r0.y, r1.y);
        unpack2(vz, r0.z, r1.z);
        unpack2(vw, r0.w, r1.w);
        op0[r] = r0;
        op1[r] = r1;
    }
    op0[3] = make_float4(0.f, 0.f, 0.f, 1.f);
    op1[3] = make_float4(0.f, 0.f, 0.f, 1.f);
}

extern "C" void kernel_launch(void* const* d_in, const int* in_sizes, int n_in,
                              void* d_out, int out_size)
{
    const float* mc   = (const float*)d_in[0];
    const float* W1   = (const float*)d_in[1];
    const float* b1   = (const float*)d_in[2];
    const float* W2   = (const float*)d_in[3];
    const float* b2   = (const float*)d_in[4];
    const float* W3   = (const float*)d_in[5];
    const float* b3   = (const float*)d_in[6];
    const float* W4   = (const float*)d_in[7];
    const float* b4   = (const float*)d_in[8];
    const float* W5   = (const float*)d_in[9];
    const float* b5   = (const float*)d_in[10];
    const float* tw   = (const float*)d_in[11];
    const float* ip   = (const float*)d_in[12];
    const float* irpy = (const float*)d_in[13];
    float* out = (float*)d_out;

    const int B = in_sizes[0] / 4;
    const int elems_per_block = 2 * BLK;
    const int grid = (B + elems_per_block - 1) / elems_per_block;
    fk_kernel<<<grid, BLK>>>(mc, W1, b1, W2, b2, W3, b3, W4, b4, W5, b5,
                             tw, ip, irpy, out, B);
}

// round 17
// speedup vs baseline: 2.9312x; 2.9312x over previous
#include <cuda_runtime.h>
#include <cuda_bf16.h>
#include <math.h>

#define BLK 128
#define NJ 12

typedef unsigned int u32;

// ---- bf16 split helpers ----
__device__ __forceinline__ void bsplit(float v, u32& hraw, float& lo) {
    u32 u = __float_as_uint(v);
    u32 r = (u + 0x7FFFu + ((u >> 16) & 1u)) & 0xFFFF0000u;   // RN to bf16
    hraw = r >> 16;
    lo = v - __uint_as_float(r);
}
__device__ __forceinline__ u32 pack_bf16x2(float v0, float v1) {  // low half = v0
    u32 r; asm("cvt.rn.bf16x2.f32 %0, %1, %2;" : "=r"(r) : "f"(v1), "f"(v0));
    return r;
}
__device__ __forceinline__ void split_pair(float v0, float v1, u32& hi, u32& lo) {
    u32 h0, h1; float l0, l1;
    bsplit(v0, h0, l0); bsplit(v1, h1, l1);
    hi = h0 | (h1 << 16);
    lo = pack_bf16x2(l0, l1);
}

// ---- HMMA m16n8k16 bf16 (base-arch instruction, no 'a' suffix needed) ----
__device__ __forceinline__ void mma_bf16(float d[4], u32 a0, u32 a1, u32 a2, u32 a3,
                                         u32 b0, u32 b1) {
    asm volatile("mma.sync.aligned.m16n8k16.row.col.f32.bf16.bf16.f32 "
                 "{%0,%1,%2,%3}, {%4,%5,%6,%7}, {%8,%9}, {%0,%1,%2,%3};"
                 : "+f"(d[0]), "+f"(d[1]), "+f"(d[2]), "+f"(d[3])
                 : "r"(a0), "r"(a1), "r"(a2), "r"(a3), "r"(b0), "r"(b1));
}

// B fragment: B[k][n] = W[n][k]; W stored row-major [N][S] bf16 (S = padded K)
__device__ __forceinline__ void load_b(const __nv_bfloat16* sW, int S, int nt, int ks,
                                       int lane, u32& b0, u32& b1) {
    const int n = nt * 8 + (lane >> 2);
    const int k = ks * 16 + ((lane & 3) << 1);
    b0 = *reinterpret_cast<const u32*>(sW + n * S + k);
    b1 = *reinterpret_cast<const u32*>(sW + n * S + k + 8);
}

// Generic layer: D = relu(A @ W^T + b), fragments stay in registers.
// Input act pairs iH0/iL0 (rows r) and iH1/iL1 (rows r+8), indexed by prev n-tile.
template<int KT, int NT>
__device__ __forceinline__ void mlp_layer(
    const __nv_bfloat16* Wh, const __nv_bfloat16* Wl, const int S,
    const float* bias, const int lane,
    const u32 (&iH0)[2][2 * KT], const u32 (&iL0)[2][2 * KT],
    const u32 (&iH1)[2][2 * KT], const u32 (&iL1)[2][2 * KT],
    u32 (&oH0)[2][NT], u32 (&oL0)[2][NT],
    u32 (&oH1)[2][NT], u32 (&oL1)[2][NT])
{
    const int cq = (lane & 3) << 1;
    #pragma unroll
    for (int nt = 0; nt < NT; nt++) {
        u32 bh0[KT], bh1[KT], bl0[KT], bl1[KT];
        #pragma unroll
        for (int ks = 0; ks < KT; ks++) {
            load_b(Wh, S, nt, ks, lane, bh0[ks], bh1[ks]);
            load_b(Wl, S, nt, ks, lane, bl0[ks], bl1[ks]);
        }
        const float2 bp = *reinterpret_cast<const float2*>(bias + nt * 8 + cq);
        #pragma unroll
        for (int mt = 0; mt < 2; mt++) {
            float d[4] = {0.f, 0.f, 0.f, 0.f};
            #pragma unroll
            for (int ks = 0; ks < KT; ks++) {
                const u32 a0 = iH0[mt][2*ks],   a1 = iH1[mt][2*ks];
                const u32 a2 = iH0[mt][2*ks+1], a3 = iH1[mt][2*ks+1];
                mma_bf16(d, a0, a1, a2, a3, bh0[ks], bh1[ks]);
                mma_bf16(d, a0, a1, a2, a3, bl0[ks], bl1[ks]);
                mma_bf16(d, iL0[mt][2*ks], iL1[mt][2*ks],
                            iL0[mt][2*ks+1], iL1[mt][2*ks+1], bh0[ks], bh1[ks]);
            }
            const float v0 = fmaxf(d[0] + bp.x, 0.f);
            const float v1 = fmaxf(d[1] + bp.y, 0.f);
            const float v2 = fmaxf(d[2] + bp.x, 0.f);
            const float v3 = fmaxf(d[3] + bp.y, 0.f);
            split_pair(v0, v1, oH0[mt][nt], oL0[mt][nt]);
            split_pair(v2, v3, oH1[mt][nt], oL1[mt][nt]);
        }
    }
}

// padded strides (conflict-free B loads: stride%32 gives distinct banks per row)
#define S1 24
#define S2 24
#define S3 40
#define S4 72
#define S5 40
#define QSTRIDE 17

__global__ __launch_bounds__(BLK, 3)
void fk_mma_kernel(const float* __restrict__ mc,
                   const float* __restrict__ W1, const float* __restrict__ b1,
                   const float* __restrict__ W2, const float* __restrict__ b2,
                   const float* __restrict__ W3, const float* __restrict__ b3,
                   const float* __restrict__ W4, const float* __restrict__ b4,
                   const float* __restrict__ W5, const float* __restrict__ b5,
                   const float* __restrict__ twist,
                   const float* __restrict__ init_p,
                   const float* __restrict__ init_rpy,
                   float* __restrict__ out, int B)
{
    __shared__ __align__(4) __nv_bfloat16 sW1h[16 * S1], sW1l[16 * S1];
    __shared__ __align__(4) __nv_bfloat16 sW2h[32 * S2], sW2l[32 * S2];
    __shared__ __align__(4) __nv_bfloat16 sW3h[64 * S3], sW3l[64 * S3];
    __shared__ __align__(4) __nv_bfloat16 sW4h[32 * S4], sW4l[32 * S4];
    __shared__ __align__(4) __nv_bfloat16 sW5h[16 * S5], sW5l[16 * S5];
    __shared__ __align__(8) float sb1[16], sb2[32], sb3[64], sb4[32], sb5[16];
    __shared__ float sx[BLK * 4];
    __shared__ float qbuf[BLK * QSTRIDE];
    __shared__ float jwn[NJ], jru[NJ][3], jKru[NJ][3], jK2ru[NJ][3];
    __shared__ float jK[NJ][9], jK2[NJ][9], sT0[12];

    const int tid = threadIdx.x;
    const int lane = tid & 31;
    const int r = lane >> 2;
    const int cq = (lane & 3) << 1;
    const int mbase = (tid >> 5) << 5;          // warp * 32 rows

    // ---- zero padded weight arrays ----
    for (int t = tid; t < 16 * S1; t += BLK) { sW1h[t] = __nv_bfloat16(0.f); sW1l[t] = __nv_bfloat16(0.f); }
    for (int t = tid; t < 32 * S2; t += BLK) { sW2h[t] = __nv_bfloat16(0.f); sW2l[t] = __nv_bfloat16(0.f); }
    for (int t = tid; t < 64 * S3; t += BLK) { sW3h[t] = __nv_bfloat16(0.f); sW3l[t] = __nv_bfloat16(0.f); }
    for (int t = tid; t < 32 * S4; t += BLK) { sW4h[t] = __nv_bfloat16(0.f); sW4l[t] = __nv_bfloat16(0.f); }
    for (int t = tid; t < 16 * S5; t += BLK) { sW5h[t] = __nv_bfloat16(0.f); sW5l[t] = __nv_bfloat16(0.f); }
    for (int t = tid; t < 16; t += BLK) sb5[t] = 0.f;
    __syncthreads();

    // ---- stage weights as bf16 hi/lo splits ----
    {
        const float* Ws[5] = { W1, W2, W3, W4, W5 };
        __nv_bfloat16* Hs[5] = { sW1h, sW2h, sW3h, sW4h, sW5h };
        __nv_bfloat16* Ls[5] = { sW1l, sW2l, sW3l, sW4l, sW5l };
        const int Ns[5] = { 16, 32, 64, 32, 12 };
        const int Ks[5] = { 4, 16, 32, 64, 32 };
        const int Ss[5] = { S1, S2, S3, S4, S5 };
        #pragma unroll 1
        for (int L = 0; L < 5; L++) {
            const int n = Ns[L] * Ks[L];
            for (int t = tid; t < n; t += BLK) {
                const int row = t / Ks[L], col = t % Ks[L];
                u32 h; float lo;
                bsplit(Ws[L][t], h, lo);
                *reinterpret_cast<unsigned short*>(&Hs[L][row * Ss[L] + col]) = (unsigned short)h;
                Ls[L][row * Ss[L] + col] = __float2bfloat16_rn(lo);
            }
        }
    }
    for (int t = tid; t < 16; t += BLK) sb1[t] = b1[t];
    for (int t = tid; t < 32; t += BLK) sb2[t] = b2[t];
    for (int t = tid; t < 64; t += BLK) sb3[t] = b3[t];
    for (int t = tid; t < 32; t += BLK) sb4[t] = b4[t];
    for (int t = tid; t < 12; t += BLK) sb5[t] = b5[t];

    // ---- chain constants ----
    if (tid < NJ) {
        const float* tw = twist + tid * 6;
        float rx = tw[0], ry = tw[1], rz = tw[2];
        float wx = tw[3], wy = tw[4], wz = tw[5];
        float wn  = sqrtf(wx * wx + wy * wy + wz * wz + 1e-12f);
        float inv = 1.0f / wn;
        float ux = wx * inv, uy = wy * inv, uz = wz * inv;
        float rux = rx * inv, ruy = ry * inv, ruz = rz * inv;
        float K[9] = { 0.f, -uz, uy,  uz, 0.f, -ux,  -uy, ux, 0.f };
        float K2[9];
        #pragma unroll
        for (int a = 0; a < 3; a++)
            #pragma unroll
            for (int bb = 0; bb < 3; bb++)
                K2[a*3+bb] = K[a*3+0]*K[0*3+bb] + K[a*3+1]*K[1*3+bb] + K[a*3+2]*K[2*3+bb];
        jwn[tid] = wn;
        jru[tid][0] = rux; jru[tid][1] = ruy; jru[tid][2] = ruz;
        #pragma unroll
        for (int a = 0; a < 3; a++) {
            jKru[tid][a]  = K[a*3+0]*rux  + K[a*3+1]*ruy  + K[a*3+2]*ruz;
            jK2ru[tid][a] = K2[a*3+0]*rux + K2[a*3+1]*ruy + K2[a*3+2]*ruz;
        }
        #pragma unroll
        for (int e = 0; e < 9; e++) { jK[tid][e] = K[e]; jK2[tid][e] = K2[e]; }
    }
    if (tid == 32) {
        float rr = init_rpy[0], p = init_rpy[1], y = init_rpy[2];
        float cr = cosf(rr), sr = sinf(rr);
        float cp = cosf(p), sp = sinf(p);
        float cy = cosf(y), sy = sinf(y);
        sT0[0] = cy*cp;  sT0[1] = cy*sp*sr - sy*cr;  sT0[2]  = cy*sp*cr + sy*sr;  sT0[3]  = init_p[0];
        sT0[4] = sy*cp;  sT0[5] = sy*sp*sr + cy*cr;  sT0[6]  = sy*sp*cr - cy*sr;  sT0[7]  = init_p[1];
        sT0[8] = -sp;    sT0[9] = cp*sr;             sT0[10] = cp*cr;             sT0[11] = init_p[2];
    }

    // ---- stage this block's inputs ----
    int e = blockIdx.x * BLK + tid;
    if (e >= B) e = B - 1;
    {
        const float4 xv = reinterpret_cast<const float4*>(mc)[e];
        sx[tid * 4 + 0] = xv.x; sx[tid * 4 + 1] = xv.y;
        sx[tid * 4 + 2] = xv.z; sx[tid * 4 + 3] = xv.w;
    }
    __syncthreads();

    // ---- L1: build input A fragments (K=4 real, padded to 16) ----
    u32 xH0[2][2], xL0[2][2], xH1[2][2], xL1[2][2];
    #pragma unroll
    for (int mt = 0; mt < 2; mt++) {
        float v0 = 0.f, v1 = 0.f, v2 = 0.f, v3 = 0.f;
        if (cq < 4) {
            const int row = mbase + mt * 16 + r;
            v0 = sx[row * 4 + cq];       v1 = sx[row * 4 + cq + 1];
            v2 = sx[(row + 8) * 4 + cq]; v3 = sx[(row + 8) * 4 + cq + 1];
        }
        split_pair(v0, v1, xH0[mt][0], xL0[mt][0]);
        split_pair(v2, v3, xH1[mt][0], xL1[mt][0]);
        xH0[mt][1] = 0; xL0[mt][1] = 0; xH1[mt][1] = 0; xL1[mt][1] = 0;
    }

    u32 h1H0[2][2], h1L0[2][2], h1H1[2][2], h1L1[2][2];
    mlp_layer<1, 2>(sW1h, sW1l, S1, sb1, lane, xH0, xL0, xH1, xL1, h1H0, h1L0, h1H1, h1L1);

    u32 h2H0[2][4], h2L0[2][4], h2H1[2][4], h2L1[2][4];
    mlp_layer<1, 4>(sW2h, sW2l, S2, sb2, lane, h1H0, h1L0, h1H1, h1L1, h2H0, h2L0, h2H1, h2L1);

    u32 h3H0[2][8], h3L0[2][8], h3H1[2][8], h3L1[2][8];
    mlp_layer<2, 8>(sW3h, sW3l, S3, sb3, lane, h2H0, h2L0, h2H1, h2L1, h3H0, h3L0, h3H1, h3L1);

    u32 h4H0[2][4], h4L0[2][4], h4H1[2][4], h4L1[2][4];
    mlp_layer<4, 4>(sW4h, sW4l, S4, sb4, lane, h3H0, h3L0, h3H1, h3L1, h4H0, h4L0, h4H1, h4L1);

    // ---- L5: NT=2 (N padded 12->16), KT=2 -> write q to qbuf ----
    #pragma unroll
    for (int nt = 0; nt < 2; nt++) {
        u32 bh0[2], bh1[2], bl0[2], bl1[2];
        #pragma unroll
        for (int ks = 0; ks < 2; ks++) {
            load_b(sW5h, S5, nt, ks, lane, bh0[ks], bh1[ks]);
            load_b(sW5l, S5, nt, ks, lane, bl0[ks], bl1[ks]);
        }
        const float2 bp = *reinterpret_cast<const float2*>(sb5 + nt * 8 + cq);
        #pragma unroll
        for (int mt = 0; mt < 2; mt++) {
            float d[4] = {0.f, 0.f, 0.f, 0.f};
            #pragma unroll
            for (int ks = 0; ks < 2; ks++) {
                const u32 a0 = h4H0[mt][2*ks],   a1 = h4H1[mt][2*ks];
                const u32 a2 = h4H0[mt][2*ks+1], a3 = h4H1[mt][2*ks+1];
                mma_bf16(d, a0, a1, a2, a3, bh0[ks], bh1[ks]);
                mma_bf16(d, a0, a1, a2, a3, bl0[ks], bl1[ks]);
                mma_bf16(d, h4L0[mt][2*ks], h4L1[mt][2*ks],
                            h4L0[mt][2*ks+1], h4L1[mt][2*ks+1], bh0[ks], bh1[ks]);
            }
            const int n = nt * 8 + cq;
            const int row = mbase + mt * 16 + r;
            qbuf[row * QSTRIDE + n]           = fmaxf(d[0] + bp.x, 0.f);
            qbuf[row * QSTRIDE + n + 1]       = fmaxf(d[1] + bp.y, 0.f);
            qbuf[(row + 8) * QSTRIDE + n]     = fmaxf(d[2] + bp.x, 0.f);
            qbuf[(row + 8) * QSTRIDE + n + 1] = fmaxf(d[3] + bp.y, 0.f);
        }
    }
    __syncwarp();   // qbuf rows are warp-private (warp w owns rows 32w..32w+31)

    // ---- scalar SE(3) chain: thread tid = element e ----
    float q[NJ];
    #pragma unroll
    for (int j = 0; j < NJ; j++) q[j] = qbuf[tid * QSTRIDE + j];

    float T[12] = {1.f,0.f,0.f,0.f,  0.f,1.f,0.f,0.f,  0.f,0.f,1.f,0.f};
    #pragma unroll
    for (int j = 0; j < NJ; j++) {
        const float th = q[j] * jwn[j];
        float s, co;
        __sincosf(th, &s, &co);
        const float c = 1.0f - co;
        const float t = th - s;

        float R[9];
        #pragma unroll
        for (int k = 0; k < 9; k++) {
            const float dd = (k == 0 || k == 4 || k == 8) ? 1.0f : 0.0f;
            R[k] = fmaf(s, jK[j][k], fmaf(c, jK2[j][k], dd));
        }
        const float p0 = fmaf(th, jru[j][0], fmaf(c, jKru[j][0], t * jK2ru[j][0]));
        const float p1 = fmaf(th, jru[j][1], fmaf(c, jKru[j][1], t * jK2ru[j][1]));
        const float p2 = fmaf(th, jru[j][2], fmaf(c, jKru[j][2], t * jK2ru[j][2]));

        float N[12];
        #pragma unroll
        for (int rr = 0; rr < 3; rr++) {
            const float a0 = T[rr*4+0], a1 = T[rr*4+1], a2 = T[rr*4+2], a3 = T[rr*4+3];
            N[rr*4+0] = fmaf(a0, R[0], fmaf(a1, R[3], a2 * R[6]));
            N[rr*4+1] = fmaf(a0, R[1], fmaf(a1, R[4], a2 * R[7]));
            N[rr*4+2] = fmaf(a0, R[2], fmaf(a1, R[5], a2 * R[8]));
            N[rr*4+3] = fmaf(a0, p0,  fmaf(a1, p1,  fmaf(a2, p2, a3)));
        }
        #pragma unroll
        for (int k = 0; k < 12; k++) T[k] = N[k];
    }

    float4* op = reinterpret_cast<float4*>(out + (size_t)e * 16);
    #pragma unroll
    for (int rr = 0; rr < 3; rr++) {
        const float a0 = T[rr*4+0], a1 = T[rr*4+1], a2 = T[rr*4+2], a3 = T[rr*4+3];
        float4 v;
        v.x = fmaf(a0, sT0[0], fmaf(a1, sT0[4], a2 * sT0[8]));
        v.y = fmaf(a0, sT0[1], fmaf(a1, sT0[5], a2 * sT0[9]));
        v.z = fmaf(a0, sT0[2], fmaf(a1, sT0[6], a2 * sT0[10]));
        v.w = fmaf(a0, sT0[3], fmaf(a1, sT0[7], fmaf(a2, sT0[11], a3)));
        op[rr] = v;
    }
    op[3] = make_float4(0.f, 0.f, 0.f, 1.f);
}

extern "C" void kernel_launch(void* const* d_in, const int* in_sizes, int n_in,
                              void* d_out, int out_size)
{
    const float* mc   = (const float*)d_in[0];
    const float* W1   = (const float*)d_in[1];
    const float* b1   = (const float*)d_in[2];
    const float* W2   = (const float*)d_in[3];
    const float* b2   = (const float*)d_in[4];
    const float* W3   = (const float*)d_in[5];
    const float* b3   = (const float*)d_in[6];
    const float* W4   = (const float*)d_in[7];
    const float* b4   = (const float*)d_in[8];
    const float* W5   = (const float*)d_in[9];
    const float* b5   = (const float*)d_in[10];
    const float* tw   = (const float*)d_in[11];
    const float* ip   = (const float*)d_in[12];
    const float* irpy = (const float*)d_in[13];
    float* out = (float*)d_out;

    const int B = in_sizes[0] / 4;
    const int grid = (B + BLK - 1) / BLK;
    fk_mma_kernel<<<grid, BLK>>>(mc, W1, b1, W2, b2, W3, b3, W4, b4, W5, b5,
                                 tw, ip, irpy, out, B);
}